// round 2
// baseline (speedup 1.0000x reference)
#include <cuda_runtime.h>
#include <cuda_bf16.h>
#include <mma.h>

using namespace nvcuda;

// Problem constants
#define NB    4096
#define D_IN  512
#define D_FF  2048
#define D_OUT 512
#define NEXP  8
#define MAXTILES 48

// Scratch (no allocations allowed): sorted hidden activations + routing metadata
__device__ float g_h[NB * D_FF];          // 33.5 MB
__device__ int   g_perm[NB];
__device__ int   g_segStart[NEXP + 1];
__device__ int   g_tileExpert[MAXTILES];
__device__ int   g_tileRow[MAXTILES];

// ---------------------------------------------------------------------------
// Setup: histogram experts, prefix sum, scatter permutation, build tile map
// ---------------------------------------------------------------------------
__global__ void setup_kernel(const int* __restrict__ groups) {
    __shared__ int cnt[NEXP];
    __shared__ int base[NEXP];
    int tid = threadIdx.x;
    if (tid < NEXP) cnt[tid] = 0;
    __syncthreads();
    for (int b = tid; b < NB; b += blockDim.x)
        atomicAdd(&cnt[groups[2 * b]], 1);
    __syncthreads();
    if (tid == 0) {
        int s = 0;
        for (int e = 0; e < NEXP; e++) {
            g_segStart[e] = s;
            base[e] = s;
            s += cnt[e];
        }
        g_segStart[NEXP] = s;
        int t = 0;
        for (int e = 0; e < NEXP; e++) {
            for (int r = g_segStart[e]; r < g_segStart[e] + cnt[e]; r += 128) {
                g_tileExpert[t] = e;
                g_tileRow[t] = r;
                t++;
            }
        }
        for (; t < MAXTILES; t++) g_tileExpert[t] = -1;
    }
    __syncthreads();
    for (int b = tid; b < NB; b += blockDim.x) {
        int e = groups[2 * b];
        int pos = atomicAdd(&base[e], 1);
        g_perm[pos] = b;   // order within a segment is nondeterministic but output
                           // values are permutation-invariant (per-row compute).
    }
}

// ---------------------------------------------------------------------------
// Grouped GEMM, TF32 wmma. BM=128, BK=32, BN templated.
// PASS1: A = x gathered via perm, out = relu(acc+b1) -> g_h (sorted order)
// PASS2: A = g_h (sorted),          out = acc+b2 scattered via perm -> Y
// ---------------------------------------------------------------------------
template <int BN, int K, int NFULL, bool PASS1>
__launch_bounds__(256)
__global__ void gemm_kernel(const float* __restrict__ X,
                            const float* __restrict__ W,
                            const float* __restrict__ bias,
                            float* __restrict__ Y) {
    constexpr int BM = 128;
    constexpr int BK = 32;
    constexpr int WN = BN / 4;      // warp tile N (2 warps in M x 4 warps in N)
    constexpr int NF = WN / 16;     // n-fragments per warp
    constexpr int LDA = BK + 8;     // multiples of 8 floats for wmma ldm
    constexpr int LDB = BN + 8;

    int e = g_tileExpert[blockIdx.x];
    if (e < 0) return;
    int rowStart = g_tileRow[blockIdx.x];
    int segEnd   = g_segStart[e + 1];
    int n0 = blockIdx.y * BN;

    __shared__ __align__(32) float sA[BM][LDA];
    __shared__ __align__(32) float sB[BK][LDB];
    __shared__ __align__(32) float sEpi[8][256];
    __shared__ int sSrc[BM];
    __shared__ int sDst[BM];

    int tid = threadIdx.x;
    if (tid < BM) {
        int i  = rowStart + tid;
        int ic = min(i, segEnd - 1);
        if (PASS1) {
            sSrc[tid] = g_perm[ic];
            sDst[tid] = (i < segEnd) ? i : -1;
        } else {
            sSrc[tid] = ic;
            sDst[tid] = (i < segEnd) ? g_perm[i] : -1;
        }
    }
    __syncthreads();

    const float* Abase = PASS1 ? X : (const float*)g_h;
    const float* Wb = W + (size_t)e * K * NFULL;

    int warpId = tid >> 5;
    int warpM  = warpId & 1;   // 0..1
    int warpN  = warpId >> 1;  // 0..3
    int lane   = tid & 31;

    wmma::fragment<wmma::accumulator, 16, 16, 8, float> acc[4][NF];
#pragma unroll
    for (int mi = 0; mi < 4; mi++)
#pragma unroll
        for (int ni = 0; ni < NF; ni++) wmma::fill_fragment(acc[mi][ni], 0.0f);

    for (int k0 = 0; k0 < K; k0 += BK) {
        // Load A tile (BM x BK), float4 along K
#pragma unroll
        for (int f = tid; f < BM * BK / 4; f += 256) {
            int r  = f >> 3;      // 8 float4 per row
            int kq = f & 7;
            float4 v = *reinterpret_cast<const float4*>(
                Abase + (size_t)sSrc[r] * K + k0 + kq * 4);
            sA[r][kq * 4 + 0] = v.x; sA[r][kq * 4 + 1] = v.y;
            sA[r][kq * 4 + 2] = v.z; sA[r][kq * 4 + 3] = v.w;
        }
        // Load B tile (BK x BN), float4 along N
#pragma unroll
        for (int f = tid; f < BK * BN / 4; f += 256) {
            int kr = f / (BN / 4);
            int nq = f % (BN / 4);
            float4 v = *reinterpret_cast<const float4*>(
                Wb + (size_t)(k0 + kr) * NFULL + n0 + nq * 4);
            sB[kr][nq * 4 + 0] = v.x; sB[kr][nq * 4 + 1] = v.y;
            sB[kr][nq * 4 + 2] = v.z; sB[kr][nq * 4 + 3] = v.w;
        }
        __syncthreads();

#pragma unroll
        for (int kk = 0; kk < BK; kk += 8) {
            wmma::fragment<wmma::matrix_a, 16, 16, 8, wmma::precision::tf32,
                           wmma::row_major> af[4];
            wmma::fragment<wmma::matrix_b, 16, 16, 8, wmma::precision::tf32,
                           wmma::row_major> bf[NF];
#pragma unroll
            for (int mi = 0; mi < 4; mi++) {
                wmma::load_matrix_sync(af[mi], &sA[warpM * 64 + mi * 16][kk], LDA);
#pragma unroll
                for (int t = 0; t < af[mi].num_elements; t++)
                    af[mi].x[t] = wmma::__float_to_tf32(af[mi].x[t]);
            }
#pragma unroll
            for (int ni = 0; ni < NF; ni++) {
                wmma::load_matrix_sync(bf[ni], &sB[kk][warpN * WN + ni * 16], LDB);
#pragma unroll
                for (int t = 0; t < bf[ni].num_elements; t++)
                    bf[ni].x[t] = wmma::__float_to_tf32(bf[ni].x[t]);
            }
#pragma unroll
            for (int mi = 0; mi < 4; mi++)
#pragma unroll
                for (int ni = 0; ni < NF; ni++)
                    wmma::mma_sync(acc[mi][ni], af[mi], bf[ni], acc[mi][ni]);
        }
        __syncthreads();
    }

    // Epilogue: bounce each 16x16 fragment through smem, apply bias (+relu),
    // mask invalid rows, scatter (pass2) or direct store (pass1).
#pragma unroll
    for (int mi = 0; mi < 4; mi++) {
#pragma unroll
        for (int ni = 0; ni < NF; ni++) {
            wmma::store_matrix_sync(&sEpi[warpId][0], acc[mi][ni], 16,
                                    wmma::mem_row_major);
            __syncwarp();
#pragma unroll
            for (int q = 0; q < 8; q++) {
                int idx = lane + q * 32;
                int r = idx >> 4, c = idx & 15;
                int lr  = warpM * 64 + mi * 16 + r;
                int dst = sDst[lr];
                if (dst >= 0) {
                    int n = n0 + warpN * WN + ni * 16 + c;
                    float v = sEpi[warpId][idx] + bias[e * NFULL + n];
                    if (PASS1) {
                        v = fmaxf(v, 0.0f);
                        g_h[(size_t)dst * NFULL + n] = v;
                    } else {
                        Y[(size_t)dst * NFULL + n] = v;
                    }
                }
            }
            __syncwarp();
        }
    }
}

// ---------------------------------------------------------------------------
extern "C" void kernel_launch(void* const* d_in, const int* in_sizes, int n_in,
                              void* d_out, int out_size) {
    const float* x      = (const float*)d_in[0];
    const int*   groups = (const int*)d_in[1];
    const float* W1     = (const float*)d_in[2];
    const float* b1     = (const float*)d_in[3];
    const float* W2     = (const float*)d_in[4];
    const float* b2     = (const float*)d_in[5];
    float* out = (float*)d_out;

    setup_kernel<<<1, 256>>>(groups);

    // Pass 1: h = relu(x[perm] @ W1[e] + b1[e]) -> g_h   (M=4096, N=2048, K=512)
    gemm_kernel<128, D_IN, D_FF, true>
        <<<dim3(MAXTILES, D_FF / 128), 256>>>(x, W1, b1, nullptr);

    // Pass 2: out[perm] = g_h @ W2[e] + b2[e]            (M=4096, N=512, K=2048)
    gemm_kernel<64, D_FF, D_OUT, false>
        <<<dim3(MAXTILES, D_OUT / 64), 256>>>(nullptr, W2, b2, out);
}

// round 4
// speedup vs baseline: 1.4991x; 1.4991x over previous
#include <cuda_runtime.h>
#include <cuda_bf16.h>
#include <mma.h>
#include <cstdint>

using namespace nvcuda;

// Problem constants
#define NB    4096
#define D_IN  512
#define D_FF  2048
#define D_OUT 512
#define NEXP  8
#define MAXTILES 48

// Scratch (no allocations allowed): sorted hidden activations + routing metadata
__device__ float g_h[NB * D_FF];          // 33.5 MB
__device__ int   g_perm[NB];
__device__ int   g_segStart[NEXP + 1];
__device__ int   g_tileExpert[MAXTILES];
__device__ int   g_tileRow[MAXTILES];

// ---------------------------------------------------------------------------
// cp.async helpers
// ---------------------------------------------------------------------------
__device__ __forceinline__ void cp_async16(float* smem_dst, const float* gsrc) {
    unsigned int s = (unsigned int)__cvta_generic_to_shared(smem_dst);
    asm volatile("cp.async.cg.shared.global [%0], [%1], 16;\n" :: "r"(s), "l"(gsrc));
}
__device__ __forceinline__ void cp_commit() {
    asm volatile("cp.async.commit_group;\n");
}
template <int N>
__device__ __forceinline__ void cp_wait() {
    asm volatile("cp.async.wait_group %0;\n" :: "n"(N));
}

// ---------------------------------------------------------------------------
// Setup: histogram experts, prefix sum, scatter permutation, build tile map
// ---------------------------------------------------------------------------
__global__ void setup_kernel(const int* __restrict__ groups) {
    __shared__ int cnt[NEXP];
    __shared__ int base[NEXP];
    int tid = threadIdx.x;
    if (tid < NEXP) cnt[tid] = 0;
    __syncthreads();
    for (int b = tid; b < NB; b += blockDim.x)
        atomicAdd(&cnt[groups[2 * b]], 1);
    __syncthreads();
    if (tid == 0) {
        int s = 0;
        for (int e = 0; e < NEXP; e++) {
            g_segStart[e] = s;
            base[e] = s;
            s += cnt[e];
        }
        g_segStart[NEXP] = s;
        int t = 0;
        for (int e = 0; e < NEXP; e++) {
            for (int r = g_segStart[e]; r < g_segStart[e] + cnt[e]; r += 128) {
                g_tileExpert[t] = e;
                g_tileRow[t] = r;
                t++;
            }
        }
        for (; t < MAXTILES; t++) g_tileExpert[t] = -1;
    }
    __syncthreads();
    for (int b = tid; b < NB; b += blockDim.x) {
        int e = groups[2 * b];
        int pos = atomicAdd(&base[e], 1);
        g_perm[pos] = b;   // order within a segment is nondeterministic but output
                           // values are permutation-invariant (per-row compute).
    }
}

// ---------------------------------------------------------------------------
// Grouped GEMM, TF32 wmma, 2-stage cp.async double-buffered pipeline.
// BM=128, BN=128, BK=32.  8 warps: 2 in M x 4 in N, warp tile 64x32.
// PASS1: A = x gathered via perm, out = relu(acc+b1) -> g_h (sorted order)
// PASS2: A = g_h (sorted),        out = acc+b2 scattered via perm -> Y
// ---------------------------------------------------------------------------
#define BM  128
#define BN  128
#define BK  32
#define LDA (BK + 8)   // 160B row stride (mult of 32B)
#define LDB (BN + 8)   // 544B row stride (mult of 32B)
#define STAGE_FLOATS (BM * LDA + BK * LDB)   // 9472 floats = 37888 B
#define SMEM_DYN_BYTES (2 * STAGE_FLOATS * 4)  // 75776 B

template <int K, int NFULL, bool PASS1>
__launch_bounds__(256)
__global__ void gemm_kernel(const float* __restrict__ X,
                            const float* __restrict__ W,
                            const float* __restrict__ bias,
                            float* __restrict__ Y) {
    constexpr int WN = BN / 4;      // 32
    constexpr int NF = WN / 16;     // 2

    extern __shared__ __align__(128) float dynSmem[];

    __shared__ __align__(32) float sEpi[8][256];
    __shared__ int sSrc[BM];
    __shared__ int sDst[BM];

    int e = g_tileExpert[blockIdx.x];
    if (e < 0) return;
    int rowStart = g_tileRow[blockIdx.x];
    int segEnd   = g_segStart[e + 1];
    int n0 = blockIdx.y * BN;

    int tid = threadIdx.x;
    if (tid < BM) {
        int i  = rowStart + tid;
        int ic = min(i, segEnd - 1);
        if (PASS1) {
            sSrc[tid] = g_perm[ic];
            sDst[tid] = (i < segEnd) ? i : -1;
        } else {
            sSrc[tid] = ic;
            sDst[tid] = (i < segEnd) ? g_perm[i] : -1;
        }
    }
    __syncthreads();

    const float* Abase = PASS1 ? X : (const float*)g_h;
    const float* Wb = W + (size_t)e * K * NFULL;

    int warpId = tid >> 5;
    int warpM  = warpId & 1;   // 0..1
    int warpN  = warpId >> 1;  // 0..3
    int lane   = tid & 31;

    wmma::fragment<wmma::accumulator, 16, 16, 8, float> acc[4][NF];
#pragma unroll
    for (int mi = 0; mi < 4; mi++)
#pragma unroll
        for (int ni = 0; ni < NF; ni++) wmma::fill_fragment(acc[mi][ni], 0.0f);

    constexpr int NT = K / BK;   // number of K-tiles

    // --- stage loader ---
    auto loadStage = [&](int s, int k0) {
        float* sA = dynSmem + s * STAGE_FLOATS;
        float* sB = sA + BM * LDA;
#pragma unroll
        for (int f = tid; f < BM * BK / 4; f += 256) {
            int r  = f >> 3;     // 8 float4 per A row
            int kq = f & 7;
            cp_async16(&sA[r * LDA + kq * 4],
                       Abase + (size_t)sSrc[r] * K + k0 + kq * 4);
        }
#pragma unroll
        for (int f = tid; f < BK * BN / 4; f += 256) {
            int kr = f >> 5;     // BN/4 = 32 float4 per B row
            int nq = f & 31;
            cp_async16(&sB[kr * LDB + nq * 4],
                       Wb + (size_t)(k0 + kr) * NFULL + n0 + nq * 4);
        }
    };

    loadStage(0, 0);
    cp_commit();

    for (int t = 0; t < NT; t++) {
        if (t + 1 < NT) loadStage((t + 1) & 1, (t + 1) * BK);
        cp_commit();
        cp_wait<1>();
        __syncthreads();

        const float* sA = dynSmem + (t & 1) * STAGE_FLOATS;
        const float* sB = sA + BM * LDA;

#pragma unroll
        for (int kk = 0; kk < BK; kk += 8) {
            wmma::fragment<wmma::matrix_a, 16, 16, 8, wmma::precision::tf32,
                           wmma::row_major> af[4];
            wmma::fragment<wmma::matrix_b, 16, 16, 8, wmma::precision::tf32,
                           wmma::row_major> bf[NF];
#pragma unroll
            for (int mi = 0; mi < 4; mi++) {
                wmma::load_matrix_sync(af[mi],
                    &sA[(warpM * 64 + mi * 16) * LDA + kk], LDA);
#pragma unroll
                for (int q = 0; q < af[mi].num_elements; q++)
                    af[mi].x[q] = wmma::__float_to_tf32(af[mi].x[q]);
            }
#pragma unroll
            for (int ni = 0; ni < NF; ni++) {
                wmma::load_matrix_sync(bf[ni],
                    &sB[kk * LDB + warpN * WN + ni * 16], LDB);
#pragma unroll
                for (int q = 0; q < bf[ni].num_elements; q++)
                    bf[ni].x[q] = wmma::__float_to_tf32(bf[ni].x[q]);
            }
#pragma unroll
            for (int mi = 0; mi < 4; mi++)
#pragma unroll
                for (int ni = 0; ni < NF; ni++)
                    wmma::mma_sync(acc[mi][ni], af[mi], bf[ni], acc[mi][ni]);
        }
        __syncthreads();
    }

    // Epilogue: bounce each 16x16 fragment through smem, apply bias (+relu),
    // mask invalid rows, scatter (pass2) or direct store (pass1).
#pragma unroll
    for (int mi = 0; mi < 4; mi++) {
#pragma unroll
        for (int ni = 0; ni < NF; ni++) {
            wmma::store_matrix_sync(&sEpi[warpId][0], acc[mi][ni], 16,
                                    wmma::mem_row_major);
            __syncwarp();
#pragma unroll
            for (int q = 0; q < 8; q++) {
                int idx = lane + q * 32;
                int r = idx >> 4, c = idx & 15;
                int lr  = warpM * 64 + mi * 16 + r;
                int dst = sDst[lr];
                if (dst >= 0) {
                    int n = n0 + warpN * WN + ni * 16 + c;
                    float v = sEpi[warpId][idx] + bias[e * NFULL + n];
                    if (PASS1) {
                        v = fmaxf(v, 0.0f);
                        g_h[(size_t)dst * NFULL + n] = v;
                    } else {
                        Y[(size_t)dst * NFULL + n] = v;
                    }
                }
            }
            __syncwarp();
        }
    }
}

// ---------------------------------------------------------------------------
extern "C" void kernel_launch(void* const* d_in, const int* in_sizes, int n_in,
                              void* d_out, int out_size) {
    const float* x      = (const float*)d_in[0];
    const int*   groups = (const int*)d_in[1];
    const float* W1     = (const float*)d_in[2];
    const float* b1     = (const float*)d_in[3];
    const float* W2     = (const float*)d_in[4];
    const float* b2     = (const float*)d_in[5];
    float* out = (float*)d_out;

    static bool attrDone = false;
    if (!attrDone) {
        cudaFuncSetAttribute(gemm_kernel<D_IN, D_FF, true>,
                             cudaFuncAttributeMaxDynamicSharedMemorySize,
                             SMEM_DYN_BYTES);
        cudaFuncSetAttribute(gemm_kernel<D_FF, D_OUT, false>,
                             cudaFuncAttributeMaxDynamicSharedMemorySize,
                             SMEM_DYN_BYTES);
        attrDone = true;
    }

    setup_kernel<<<1, 512>>>(groups);

    // Pass 1: h = relu(x[perm] @ W1[e] + b1[e]) -> g_h   (M=4096, N=2048, K=512)
    gemm_kernel<D_IN, D_FF, true>
        <<<dim3(MAXTILES, D_FF / BN), 256, SMEM_DYN_BYTES>>>(x, W1, b1, nullptr);

    // Pass 2: out[perm] = g_h @ W2[e] + b2[e]            (M=4096, N=512, K=2048)
    gemm_kernel<D_FF, D_OUT, false>
        <<<dim3(MAXTILES, D_OUT / BN), 256, SMEM_DYN_BYTES>>>(nullptr, W2, b2, out);
}